// round 10
// baseline (speedup 1.0000x reference)
#include <cuda_runtime.h>
#include <cuda_bf16.h>
#include <cstdint>

// ---------------------------------------------------------------------------
// BiMamba: B=2, L=1024, d_model=1024, d_inner=2048, d_state=16, d_conv=4,
// dt_rank=64.
//
// Big GEMMs (in_proj / out_proj / merge) on tensor cores via mma.sync
// (compute_103-safe) with bf16 split-precision: v = hi + lo (both bf16);
// fp32 accum of hi*hi + hi*lo + lo*hi (lo*lo ~ 2^-16 dropped).
// bgemm v2: 128x256 CTA tile, 64x64 warp tile, ldmatrix.x4 fragments,
// 3-stage cp.async pipeline.
// ---------------------------------------------------------------------------

#define BSZ 2
#define SEQ 1024
#define DMODEL 1024
#define DINNER 2048
#define DSTATE 16
#define DTRANK 64
#define ML (BSZ * SEQ)          // 2048 rows
#define DBLW 96                 // dt_rank + 2*d_state

// ------------------------------ scratch (device globals) -------------------
__device__ __align__(128) float g_xz   [2][ML * 2 * DINNER];
__device__ __align__(128) float g_xc   [2][ML * DINNER];
__device__ __align__(128) float g_dblp [2][8][ML * DBLW];
__device__ __align__(128) float g_dbl  [2][ML * DBLW];
__device__ __align__(128) float g_delta[2][ML * DINNER];

__device__ __align__(128) __nv_bfloat16 g_xh [ML * DMODEL];
__device__ __align__(128) __nv_bfloat16 g_xl [ML * DMODEL];
__device__ __align__(128) __nv_bfloat16 g_iph[2][2 * DINNER * DMODEL];
__device__ __align__(128) __nv_bfloat16 g_ipl[2][2 * DINNER * DMODEL];
__device__ __align__(128) __nv_bfloat16 g_oph[2][DMODEL * DINNER];
__device__ __align__(128) __nv_bfloat16 g_opl[2][DMODEL * DINNER];
__device__ __align__(128) __nv_bfloat16 g_mwh[DMODEL * 2 * DMODEL];
__device__ __align__(128) __nv_bfloat16 g_mwl[DMODEL * 2 * DMODEL];
__device__ __align__(128) __nv_bfloat16 g_yh [2][ML * DINNER];
__device__ __align__(128) __nv_bfloat16 g_yl [2][ML * DINNER];
__device__ __align__(128) __nv_bfloat16 g_odh[ML * 2 * DMODEL];   // [f | b] cols
__device__ __align__(128) __nv_bfloat16 g_odl[ML * 2 * DMODEL];

// ------------------------------ helpers ------------------------------------
__device__ __forceinline__ uint32_t smem_u32(const void* p) {
    uint32_t a;
    asm("{ .reg .u64 t; cvta.to.shared.u64 t, %1; cvt.u32.u64 %0, t; }"
        : "=r"(a) : "l"(p));
    return a;
}

__device__ __forceinline__ void mma_bf16(float* d, const uint32_t* a, const uint32_t* b) {
    asm volatile(
        "mma.sync.aligned.m16n8k16.row.col.f32.bf16.bf16.f32 "
        "{%0,%1,%2,%3}, {%4,%5,%6,%7}, {%8,%9}, {%0,%1,%2,%3};"
        : "+f"(d[0]), "+f"(d[1]), "+f"(d[2]), "+f"(d[3])
        : "r"(a[0]), "r"(a[1]), "r"(a[2]), "r"(a[3]), "r"(b[0]), "r"(b[1]));
}

__device__ __forceinline__ void ldsm4(uint32_t* r, uint32_t addr) {
    asm volatile("ldmatrix.sync.aligned.m8n8.x4.shared.b16 {%0,%1,%2,%3}, [%4];"
                 : "=r"(r[0]), "=r"(r[1]), "=r"(r[2]), "=r"(r[3]) : "r"(addr));
}

// ---------------------------------------------------------------------------
// Split-precision mma.sync GEMM v2:  C[m,n] = sum_k A[m,k]*B[n,k]  (NT)
// CTA tile 128x256, 8 warps (2x4 of 64x64), BK=32, 3-stage cp.async,
// ldmatrix.x4 fragment loads.  Output fp32 C, or bf16 hi/lo split (Ch/Cl).
// Requires M%128==0, N%256==0, K%32==0 (true for all call sites).
// ---------------------------------------------------------------------------
#define PA 40                                  // smem pitch (bf16), 80B rows
#define A_ELEMS (128 * PA)                     // 5120
#define B_ELEMS (256 * PA)                     // 10240
#define STG (2 * A_ELEMS + 2 * B_ELEMS)        // 30720 elems = 61440 B
#define NSTG 3
#define BG_SMEM_BYTES (NSTG * STG * 2)         // 184320

__global__ void __launch_bounds__(256)
bgemm(const __nv_bfloat16* __restrict__ Ah, const __nv_bfloat16* __restrict__ Al, int lda,
      const __nv_bfloat16* __restrict__ Bh, const __nv_bfloat16* __restrict__ Bl, int ldb,
      float* __restrict__ C, __nv_bfloat16* __restrict__ Ch, __nv_bfloat16* __restrict__ Cl,
      int ldc, int K)
{
    extern __shared__ __align__(16) __nv_bfloat16 smem[];   // NSTG stages

    const int tid  = threadIdx.x;
    const int lane = tid & 31;
    const int wid  = tid >> 5;
    const int wm   = (wid & 1) * 64;       // warp m-offset
    const int wn   = (wid >> 1) * 64;      // warp n-offset
    const int m0   = blockIdx.y * 128;
    const int n0   = blockIdx.x * 256;
    const int NC   = K >> 5;               // 32-wide K chunks
    const uint32_t sb = smem_u32(smem);

    // ---- per-thread cp.async assignment: 12 x 16B per stage ----
    const __nv_bfloat16* gsrc[12];
    uint32_t sdst[12];
#pragma unroll
    for (int j = 0; j < 12; j++) {
        int ci = tid + j * 256;                   // 0..3071
        int mat, row, c8; uint32_t selem;
        const __nv_bfloat16* g;
        if (ci < 1024) {                          // Ah | Al : 512 chunks each
            mat = ci >> 9;
            int idx = ci & 511;
            row = idx >> 2; c8 = (idx & 3) * 8;
            g = (mat ? Al : Ah) + (size_t)(m0 + row) * lda + c8;
            selem = (uint32_t)(mat * A_ELEMS + row * PA + c8);
        } else {                                  // Bh | Bl : 1024 chunks each
            int u = ci - 1024;
            mat = u >> 10;
            int idx = u & 1023;
            row = idx >> 2; c8 = (idx & 3) * 8;
            g = (mat ? Bl : Bh) + (size_t)(n0 + row) * ldb + c8;
            selem = (uint32_t)(2 * A_ELEMS + mat * B_ELEMS + row * PA + c8);
        }
        gsrc[j] = g;
        sdst[j] = sb + selem * 2u;
    }

#define BG_LOAD(stage, kbase) do {                                              \
    const uint32_t _so = (uint32_t)(stage) * (STG * 2);                         \
    _Pragma("unroll")                                                           \
    for (int j = 0; j < 12; j++)                                                \
        asm volatile("cp.async.cg.shared.global [%0], [%1], 16;"                \
                     :: "r"(sdst[j] + _so), "l"(gsrc[j] + (kbase)) : "memory"); \
    asm volatile("cp.async.commit_group;" ::: "memory");                        \
} while (0)

    float acc[4][8][4];
#pragma unroll
    for (int mi = 0; mi < 4; mi++)
#pragma unroll
        for (int nj = 0; nj < 8; nj++)
#pragma unroll
            for (int q = 0; q < 4; q++) acc[mi][nj][q] = 0.f;

    // ldmatrix per-lane offsets (elements)
    const uint32_t aoff = (uint32_t)((((lane & 7) + ((lane >> 3) & 1) * 8) * PA) +
                                     ((lane >> 4) * 8));
    const uint32_t boff = (uint32_t)((((lane & 7) + (lane >> 4) * 8) * PA) +
                                     (((lane >> 3) & 1) * 8));

    BG_LOAD(0, 0);
    BG_LOAD(1, 32);

    for (int c = 0; c < NC; c++) {
        if (c + 1 < NC) { asm volatile("cp.async.wait_group 1;" ::: "memory"); }
        else            { asm volatile("cp.async.wait_group 0;" ::: "memory"); }
        __syncthreads();

        if (c + 2 < NC) {
            int s = c + 2; while (s >= NSTG) s -= NSTG;
            BG_LOAD(s, (c + 2) << 5);
        }

        int cs = c; while (cs >= NSTG) cs -= NSTG;
        const uint32_t st  = sb + (uint32_t)cs * (STG * 2);
        const uint32_t sAh = st;
        const uint32_t sAl = st + A_ELEMS * 2;
        const uint32_t sBh = st + 2 * A_ELEMS * 2;
        const uint32_t sBl = sBh + B_ELEMS * 2;

#pragma unroll
        for (int ks = 0; ks < 32; ks += 16) {
            uint32_t ah[4][4], al[4][4], bh[4][4], bl[4][4];
#pragma unroll
            for (int mi = 0; mi < 4; mi++) {
                const uint32_t rbase = (uint32_t)((wm + mi * 16) * PA + ks);
                ldsm4(ah[mi], sAh + (rbase + aoff) * 2u);
                ldsm4(al[mi], sAl + (rbase + aoff) * 2u);
            }
#pragma unroll
            for (int p = 0; p < 4; p++) {
                const uint32_t rbase = (uint32_t)((wn + p * 16) * PA + ks);
                ldsm4(bh[p], sBh + (rbase + boff) * 2u);
                ldsm4(bl[p], sBl + (rbase + boff) * 2u);
            }
#pragma unroll
            for (int mi = 0; mi < 4; mi++)
#pragma unroll
                for (int nj = 0; nj < 8; nj++) {
                    const uint32_t* bhp = &bh[nj >> 1][(nj & 1) * 2];
                    const uint32_t* blp = &bl[nj >> 1][(nj & 1) * 2];
                    mma_bf16(acc[mi][nj], ah[mi], bhp);
                    mma_bf16(acc[mi][nj], ah[mi], blp);
                    mma_bf16(acc[mi][nj], al[mi], bhp);
                }
        }
    }

    // ---- epilogue ----
    const int r   = lane >> 2;
    const int cp2 = (lane & 3) * 2;
#pragma unroll
    for (int mi = 0; mi < 4; mi++) {
        const int m = m0 + wm + mi * 16 + r;
#pragma unroll
        for (int nj = 0; nj < 8; nj++) {
            const int n = n0 + wn + nj * 8 + cp2;
            const float* d = acc[mi][nj];
            if (C != nullptr) {
                float2 v0; v0.x = d[0]; v0.y = d[1];
                float2 v1; v1.x = d[2]; v1.y = d[3];
                *(float2*)(C + (size_t)m * ldc + n)       = v0;
                *(float2*)(C + (size_t)(m + 8) * ldc + n) = v1;
            } else {
#pragma unroll
                for (int half = 0; half < 2; half++) {
                    const float v0 = d[half * 2], v1 = d[half * 2 + 1];
                    const int mm = m + half * 8;
                    __nv_bfloat16 h0 = __float2bfloat16(v0);
                    __nv_bfloat16 h1 = __float2bfloat16(v1);
                    __nv_bfloat162 hp; hp.x = h0; hp.y = h1;
                    __nv_bfloat162 lp;
                    lp.x = __float2bfloat16(v0 - __bfloat162float(h0));
                    lp.y = __float2bfloat16(v1 - __bfloat162float(h1));
                    *(__nv_bfloat162*)(Ch + (size_t)mm * ldc + n) = hp;
                    *(__nv_bfloat162*)(Cl + (size_t)mm * ldc + n) = lp;
                }
            }
        }
    }
#undef BG_LOAD
}

// ---------------------------------------------------------------------------
// fp32 -> (hi, lo) bf16 split, 2-wide vectorized.
// ---------------------------------------------------------------------------
__global__ void split2(const float* __restrict__ src,
                       __nv_bfloat16* __restrict__ h, __nv_bfloat16* __restrict__ l,
                       int n2)
{
    int i = blockIdx.x * 256 + threadIdx.x;
    if (i < n2) {
        float2 v = ((const float2*)src)[i];
        __nv_bfloat16 h0 = __float2bfloat16(v.x);
        __nv_bfloat16 h1 = __float2bfloat16(v.y);
        __nv_bfloat162 hp; hp.x = h0; hp.y = h1;
        __nv_bfloat162 lp;
        lp.x = __float2bfloat16(v.x - __bfloat162float(h0));
        lp.y = __float2bfloat16(v.y - __bfloat162float(h1));
        ((__nv_bfloat162*)h)[i] = hp;
        ((__nv_bfloat162*)l)[i] = lp;
    }
}

// ---------------------------------------------------------------------------
// fp32 SGEMM (delta GEMM, K=64).  flags bit1 = add bias[n] then softplus.
// ---------------------------------------------------------------------------
__global__ void __launch_bounds__(256)
sgemm_nt(const float* __restrict__ A, int lda,
         const float* __restrict__ B, int ldb,
         float* __restrict__ C, int ldc,
         int K, const float* __restrict__ bias, int flags)
{
    __shared__ float As[8][128];
    __shared__ float Bs[8][128];

    const int tid = threadIdx.x;
    const int m0 = blockIdx.y * 128;
    const int n0 = blockIdx.x * 128;

    const int arow = tid >> 1;
    const int acol = (tid & 1) * 4;
    const float* Aptr = A + (size_t)(m0 + arow) * lda + acol;
    const float* Bptr = B + (size_t)(n0 + arow) * ldb + acol;

    const int tx = tid & 15;
    const int ty = tid >> 4;

    float acc[8][8];
#pragma unroll
    for (int i = 0; i < 8; i++)
#pragma unroll
        for (int j = 0; j < 8; j++) acc[i][j] = 0.f;

    for (int kt = 0; kt < K; kt += 8) {
        float4 av = *(const float4*)(Aptr + kt);
        float4 bv = *(const float4*)(Bptr + kt);
        __syncthreads();
        As[acol + 0][arow] = av.x; As[acol + 1][arow] = av.y;
        As[acol + 2][arow] = av.z; As[acol + 3][arow] = av.w;
        Bs[acol + 0][arow] = bv.x; Bs[acol + 1][arow] = bv.y;
        Bs[acol + 2][arow] = bv.z; Bs[acol + 3][arow] = bv.w;
        __syncthreads();
#pragma unroll
        for (int k = 0; k < 8; k++) {
            float a[8], b[8];
            *(float4*)&a[0] = *(const float4*)&As[k][ty * 8];
            *(float4*)&a[4] = *(const float4*)&As[k][ty * 8 + 4];
            *(float4*)&b[0] = *(const float4*)&Bs[k][tx * 8];
            *(float4*)&b[4] = *(const float4*)&Bs[k][tx * 8 + 4];
#pragma unroll
            for (int i = 0; i < 8; i++)
#pragma unroll
                for (int j = 0; j < 8; j++)
                    acc[i][j] += a[i] * b[j];
        }
    }

#pragma unroll
    for (int i = 0; i < 8; i++) {
        const int m = m0 + ty * 8 + i;
        float* crow = C + (size_t)m * ldc + n0 + tx * 8;
#pragma unroll
        for (int j = 0; j < 8; j++) {
            float v = acc[i][j];
            if (flags & 2) {
                v += bias[n0 + tx * 8 + j];
                v = (v > 20.f) ? v : log1pf(__expf(v));
            }
            acc[i][j] = v;
        }
        *(float4*)crow       = *(float4*)&acc[i][0];
        *(float4*)(crow + 4) = *(float4*)&acc[i][4];
    }
}

// ---------------------------------------------------------------------------
// Skinny GEMM for x_proj: M=2048, N=96, K=2048, split-K over gridDim.y=8.
// ---------------------------------------------------------------------------
__global__ void __launch_bounds__(256)
sgemm_skinny96(const float* __restrict__ A, int lda,
               const float* __restrict__ B, int ldb,
               float* __restrict__ Cpart, int K)
{
    __shared__ float As[16][128];
    __shared__ float Bs[16][96];

    const int tid = threadIdx.x;
    const int m0 = blockIdx.x * 128;
    const int kchunk = K >> 3;
    const int kbase = blockIdx.y * kchunk;
    float* C = Cpart + (size_t)blockIdx.y * (ML * DBLW);

    const int tx = tid & 15;
    const int ty = tid >> 4;

    float acc[8][6];
#pragma unroll
    for (int i = 0; i < 8; i++)
#pragma unroll
        for (int j = 0; j < 6; j++) acc[i][j] = 0.f;

    for (int kt = 0; kt < kchunk; kt += 16) {
        __syncthreads();
#pragma unroll
        for (int f = 0; f < 2; f++) {
            int fid = tid + f * 256;
            int row = fid >> 2, c4 = (fid & 3) * 4;
            float4 v = *(const float4*)(A + (size_t)(m0 + row) * lda + kbase + kt + c4);
            As[c4 + 0][row] = v.x; As[c4 + 1][row] = v.y;
            As[c4 + 2][row] = v.z; As[c4 + 3][row] = v.w;
        }
#pragma unroll
        for (int f = 0; f < 2; f++) {
            int fid = tid + f * 256;
            if (fid < 384) {
                int row = fid >> 2, c4 = (fid & 3) * 4;
                float4 v = *(const float4*)(B + (size_t)row * ldb + kbase + kt + c4);
                Bs[c4 + 0][row] = v.x; Bs[c4 + 1][row] = v.y;
                Bs[c4 + 2][row] = v.z; Bs[c4 + 3][row] = v.w;
            }
        }
        __syncthreads();
#pragma unroll
        for (int k = 0; k < 16; k++) {
            float a[8], b[6];
            *(float4*)&a[0] = *(const float4*)&As[k][ty * 8];
            *(float4*)&a[4] = *(const float4*)&As[k][ty * 8 + 4];
#pragma unroll
            for (int j = 0; j < 6; j++) b[j] = Bs[k][tx * 6 + j];
#pragma unroll
            for (int i = 0; i < 8; i++)
#pragma unroll
                for (int j = 0; j < 6; j++)
                    acc[i][j] += a[i] * b[j];
        }
    }
#pragma unroll
    for (int i = 0; i < 8; i++)
#pragma unroll
        for (int j = 0; j < 6; j++)
            C[(size_t)(m0 + ty * 8 + i) * DBLW + tx * 6 + j] = acc[i][j];
}

__global__ void reduce_dbl()
{
    int i = blockIdx.x * 256 + threadIdx.x;
    if (i < 2 * ML * DBLW) {
        int d = i / (ML * DBLW);
        int j = i - d * (ML * DBLW);
        float s = 0.f;
#pragma unroll
        for (int p = 0; p < 8; p++) s += g_dblp[d][p][j];
        g_dbl[d][j] = s;
    }
}

// ---------------------------------------------------------------------------
// Depthwise conv (d_conv=4) + SiLU.
// ---------------------------------------------------------------------------
__global__ void conv_silu_kernel(const float* __restrict__ cwf, const float* __restrict__ cbf,
                                 const float* __restrict__ cwb, const float* __restrict__ cbb)
{
    const int dir = blockIdx.y;
    const int idx = blockIdx.x * 256 + threadIdx.x;
    const int e = idx & (DINNER - 1);
    const int bl = idx >> 11;
    const int l = bl & (SEQ - 1);

    const float* xz = g_xz[dir];
    const float* cw = dir ? cwb : cwf;
    const float* cb = dir ? cbb : cbf;

    float s = cb[e];
    const float* base = xz + (size_t)(bl - l) * (2 * DINNER) + e;
#pragma unroll
    for (int k = 0; k < 4; k++) {
        int ls = dir ? (l + 3 - k) : (l + k - 3);
        if (ls >= 0 && ls < SEQ)
            s += cw[e * 4 + k] * base[(size_t)ls * (2 * DINNER)];
    }
    g_xc[dir][idx] = s * (1.0f / (1.0f + __expf(-s)));
}

// ---------------------------------------------------------------------------
// Selective scan + gating; epilogue writes y as bf16 hi/lo split.
// ---------------------------------------------------------------------------
__global__ void __launch_bounds__(128)
scan_kernel(const float* __restrict__ alogf, const float* __restrict__ Df,
            const float* __restrict__ alogb, const float* __restrict__ Db)
{
    const int dir = blockIdx.y;
    const int lane16 = threadIdx.x & 15;
    const int ch = (blockIdx.x * 128 + threadIdx.x) >> 4;
    const int b = ch >> 11;
    const int e = ch & (DINNER - 1);

    const float* alog = dir ? alogb : alogf;
    const float* Dvp  = dir ? Db : Df;

    const float A  = -__expf(alog[e * DSTATE + lane16]);
    const float Dv = Dvp[e];

    const float* delta = g_delta[dir];
    const float* xc    = g_xc[dir];
    const float* dbl   = g_dbl[dir];
    const float* zb    = g_xz[dir];
    __nv_bfloat16* yh  = g_yh[dir];
    __nv_bfloat16* yl  = g_yl[dir];

    float h = 0.f;
    int l = dir ? (SEQ - 1) : 0;
    const int lstep = dir ? -1 : 1;

#pragma unroll 2
    for (int t = 0; t < SEQ; t++, l += lstep) {
        const int bl = b * SEQ + l;
        const float dl  = delta[(size_t)bl * DINNER + e];
        const float xcv = xc[(size_t)bl * DINNER + e];
        const float Bv  = dbl[bl * DBLW + DTRANK + lane16];
        const float Cv  = dbl[bl * DBLW + DTRANK + DSTATE + lane16];

        const float dA = __expf(dl * A);
        h = dA * h + (dl * xcv) * Bv;
        float p = h * Cv;
        p += __shfl_xor_sync(0xffffffffu, p, 1);
        p += __shfl_xor_sync(0xffffffffu, p, 2);
        p += __shfl_xor_sync(0xffffffffu, p, 4);
        p += __shfl_xor_sync(0xffffffffu, p, 8);
        if (lane16 == 0) {
            const float zv = zb[(size_t)bl * (2 * DINNER) + DINNER + e];
            const float gate = zv * (1.0f / (1.0f + __expf(-zv)));
            const float yv = (p + xcv * Dv) * gate;
            __nv_bfloat16 hv = __float2bfloat16(yv);
            yh[(size_t)bl * DINNER + e] = hv;
            yl[(size_t)bl * DINNER + e] = __float2bfloat16(yv - __bfloat162float(hv));
        }
    }
}

// ---------------------------------------------------------------------------
extern "C" void kernel_launch(void* const* d_in, const int* in_sizes, int n_in,
                              void* d_out, int out_size)
{
    const float* x = (const float*)d_in[0];
    const float* ip[2]   = {(const float*)d_in[1],  (const float*)d_in[10]};
    const float* cw[2]   = {(const float*)d_in[2],  (const float*)d_in[11]};
    const float* cb[2]   = {(const float*)d_in[3],  (const float*)d_in[12]};
    const float* xpj[2]  = {(const float*)d_in[4],  (const float*)d_in[13]};
    const float* dtw[2]  = {(const float*)d_in[5],  (const float*)d_in[14]};
    const float* dtb[2]  = {(const float*)d_in[6],  (const float*)d_in[15]};
    const float* alog[2] = {(const float*)d_in[7],  (const float*)d_in[16]};
    const float* Dp[2]   = {(const float*)d_in[8],  (const float*)d_in[17]};
    const float* op[2]   = {(const float*)d_in[9],  (const float*)d_in[18]};
    const float* mw = (const float*)d_in[19];

    float *xz, *xc, *dblp, *dbl, *delta;
    __nv_bfloat16 *xh, *xl, *iph, *ipl, *oph, *opl, *mwh, *mwl, *yh, *yl, *odh, *odl;
    cudaGetSymbolAddress((void**)&xz,    g_xz);
    cudaGetSymbolAddress((void**)&xc,    g_xc);
    cudaGetSymbolAddress((void**)&dblp,  g_dblp);
    cudaGetSymbolAddress((void**)&dbl,   g_dbl);
    cudaGetSymbolAddress((void**)&delta, g_delta);
    cudaGetSymbolAddress((void**)&xh,    g_xh);
    cudaGetSymbolAddress((void**)&xl,    g_xl);
    cudaGetSymbolAddress((void**)&iph,   g_iph);
    cudaGetSymbolAddress((void**)&ipl,   g_ipl);
    cudaGetSymbolAddress((void**)&oph,   g_oph);
    cudaGetSymbolAddress((void**)&opl,   g_opl);
    cudaGetSymbolAddress((void**)&mwh,   g_mwh);
    cudaGetSymbolAddress((void**)&mwl,   g_mwl);
    cudaGetSymbolAddress((void**)&yh,    g_yh);
    cudaGetSymbolAddress((void**)&yl,    g_yl);
    cudaGetSymbolAddress((void**)&odh,   g_odh);
    cudaGetSymbolAddress((void**)&odl,   g_odl);

    cudaFuncSetAttribute(bgemm, cudaFuncAttributeMaxDynamicSharedMemorySize, BG_SMEM_BYTES);

    const size_t SZ_XZ  = (size_t)ML * 2 * DINNER;
    const size_t SZ_E   = (size_t)ML * DINNER;
    const size_t SZ_DBL = (size_t)ML * DBLW;
    const size_t SZ_IP  = (size_t)2 * DINNER * DMODEL;
    const size_t SZ_OP  = (size_t)DMODEL * DINNER;

    // 0) bf16 hi/lo splits of x and weights
    {
        int n2;
        n2 = ML * DMODEL / 2;
        split2<<<(n2 + 255) / 256, 256>>>(x, xh, xl, n2);
        n2 = (int)(SZ_IP / 2);
        for (int d = 0; d < 2; d++)
            split2<<<(n2 + 255) / 256, 256>>>(ip[d], iph + d * SZ_IP, ipl + d * SZ_IP, n2);
        n2 = (int)(SZ_OP / 2);
        for (int d = 0; d < 2; d++)
            split2<<<(n2 + 255) / 256, 256>>>(op[d], oph + d * SZ_OP, opl + d * SZ_OP, n2);
        n2 = DMODEL * 2 * DMODEL / 2;
        split2<<<(n2 + 255) / 256, 256>>>(mw, mwh, mwl, n2);
    }

    // 1) input projections (tensor cores): xz = x @ in_proj^T   (2048 x 4096)
    for (int d = 0; d < 2; d++)
        bgemm<<<dim3(2 * DINNER / 256, ML / 128), 256, BG_SMEM_BYTES>>>(
            xh, xl, DMODEL, iph + d * SZ_IP, ipl + d * SZ_IP, DMODEL,
            xz + d * SZ_XZ, nullptr, nullptr, 2 * DINNER, DMODEL);

    // 2) depthwise conv + silu
    conv_silu_kernel<<<dim3(ML * DINNER / 256, 2), 256>>>(cw[0], cb[0], cw[1], cb[1]);

    // 3) x_proj (skinny, split-K=8) + reduce
    for (int d = 0; d < 2; d++)
        sgemm_skinny96<<<dim3(ML / 128, 8), 256>>>(
            xc + d * SZ_E, DINNER, xpj[d], DINNER,
            dblp + (size_t)d * 8 * SZ_DBL, DINNER);
    reduce_dbl<<<(2 * ML * DBLW + 255) / 256, 256>>>();

    // 4) delta = softplus(dt @ dt_w^T + dt_b)   (fp32, K=64)
    for (int d = 0; d < 2; d++)
        sgemm_nt<<<dim3(DINNER / 128, ML / 128), 256>>>(
            dbl + d * SZ_DBL, DBLW, dtw[d], DTRANK,
            delta + d * SZ_E, DINNER, DTRANK, dtb[d], 2);

    // 5) selective scan + gating (writes y as bf16 hi/lo)
    scan_kernel<<<dim3(BSZ * DINNER * DSTATE / 128, 2), 128>>>(
        alog[0], Dp[0], alog[1], Dp[1]);

    // 6) output projections (tensor cores): od[:, d*1024:(d+1)*1024] = y @ op^T
    //    written as bf16 hi/lo into the concatenated od buffer (ldc = 2048).
    for (int d = 0; d < 2; d++)
        bgemm<<<dim3(DMODEL / 256, ML / 128), 256, BG_SMEM_BYTES>>>(
            yh + d * SZ_E, yl + d * SZ_E, DINNER,
            oph + d * SZ_OP, opl + d * SZ_OP, DINNER,
            nullptr, odh + d * DMODEL, odl + d * DMODEL, 2 * DMODEL, DINNER);

    // 7) merge (tensor cores): out = odcat @ merge_w^T   (K = 2048, single GEMM)
    bgemm<<<dim3(DMODEL / 256, ML / 128), 256, BG_SMEM_BYTES>>>(
        odh, odl, 2 * DMODEL, mwh, mwl, 2 * DMODEL,
        (float*)d_out, nullptr, nullptr, DMODEL, 2 * DMODEL);
}

// round 13
// speedup vs baseline: 1.2524x; 1.2524x over previous
#include <cuda_runtime.h>
#include <cuda_fp16.h>
#include <cuda_bf16.h>
#include <cstdint>

// ---------------------------------------------------------------------------
// BiMamba: B=2, L=1024, d_model=1024, d_inner=2048, d_state=16, d_conv=4,
// dt_rank=64.
//
// Big GEMMs (in_proj / out_proj / merge) on tensor cores via mma.sync fp16
// 2-product split precision:  a = ah + al (both fp16, 22 mantissa bits),
// b ~= bh (fp16 round, rel err 2^-12);  C = ah*bh + al*bh = a*bh.
// fp32 accumulators.  Physical MACs = 2x logical (was 3x with bf16 scheme).
// Small GEMMs (x_proj skinny, dt_w) + conv + scan stay fp32 CUDA-core.
// ---------------------------------------------------------------------------

#define BSZ 2
#define SEQ 1024
#define DMODEL 1024
#define DINNER 2048
#define DSTATE 16
#define DTRANK 64
#define ML (BSZ * SEQ)          // 2048 rows
#define DBLW 96                 // dt_rank + 2*d_state

// ------------------------------ scratch (device globals) -------------------
__device__ __align__(128) float g_xz   [2][ML * 2 * DINNER];
__device__ __align__(128) float g_xc   [2][ML * DINNER];
__device__ __align__(128) float g_dblp [2][8][ML * DBLW];
__device__ __align__(128) float g_dbl  [2][ML * DBLW];
__device__ __align__(128) float g_delta[2][ML * DINNER];

__device__ __align__(128) __half g_xh [ML * DMODEL];
__device__ __align__(128) __half g_xl [ML * DMODEL];
__device__ __align__(128) __half g_iph[2][2 * DINNER * DMODEL];   // B-side: hi only
__device__ __align__(128) __half g_oph[2][DMODEL * DINNER];
__device__ __align__(128) __half g_mwh[DMODEL * 2 * DMODEL];
__device__ __align__(128) __half g_yh [2][ML * DINNER];
__device__ __align__(128) __half g_yl [2][ML * DINNER];
__device__ __align__(128) __half g_odh[ML * 2 * DMODEL];          // [f | b] cols
__device__ __align__(128) __half g_odl[ML * 2 * DMODEL];

// ------------------------------ helpers ------------------------------------
__device__ __forceinline__ uint32_t smem_u32(const void* p) {
    uint32_t a;
    asm("{ .reg .u64 t; cvta.to.shared.u64 t, %1; cvt.u32.u64 %0, t; }"
        : "=r"(a) : "l"(p));
    return a;
}

__device__ __forceinline__ void mma_f16(float* d, const uint32_t* a, const uint32_t* b) {
    asm volatile(
        "mma.sync.aligned.m16n8k16.row.col.f32.f16.f16.f32 "
        "{%0,%1,%2,%3}, {%4,%5,%6,%7}, {%8,%9}, {%0,%1,%2,%3};"
        : "+f"(d[0]), "+f"(d[1]), "+f"(d[2]), "+f"(d[3])
        : "r"(a[0]), "r"(a[1]), "r"(a[2]), "r"(a[3]), "r"(b[0]), "r"(b[1]));
}

// ---------------------------------------------------------------------------
// fp16 2-product mma.sync GEMM:  C[m,n] = sum_k A[m,k]*B[n,k]  (NT, row-major)
// A given as fp16 (hi,lo) pair; B as fp16 hi.  CTA tile 128x128, K-chunk 32,
// 256 threads (8 warps, 64x32 warp tiles), 2-stage cp.async pipeline.
// Output: fp32 C, or fp16 hi/lo split (Ch/Cl).
// Requires M%128==0, N%128==0, K%32==0 (true for all call sites).
// ---------------------------------------------------------------------------
#define PITCH 40                              // fp16 elems per smem row (pad)
#define MAT_ELEMS (128 * PITCH)               // 5120 per matrix
#define STG_ELEMS (3 * MAT_ELEMS)             // Ah | Al | Bh
#define BG_SMEM_BYTES (2 * STG_ELEMS * 2)     // 61440 bytes

__global__ void __launch_bounds__(256, 2)
bgemm(const __half* __restrict__ Ah, const __half* __restrict__ Al, int lda,
      const __half* __restrict__ Bh, int ldb,
      float* __restrict__ C, __half* __restrict__ Ch, __half* __restrict__ Cl,
      int ldc, int K)
{
    extern __shared__ __align__(16) __half smem[];   // 2 stages

    const int tid  = threadIdx.x;
    const int lane = tid & 31;
    const int wid  = tid >> 5;
    const int wm   = (wid & 1) * 64;      // warp m-offset within CTA tile
    const int wn   = (wid >> 1) * 32;     // warp n-offset
    const int m0   = blockIdx.y * 128;
    const int n0   = blockIdx.x * 128;
    const int NC   = K >> 5;              // chunks of 32

    // ---- fixed per-thread load assignment: 6x cp.async.cg (16B each) ----
    const __half* gsrc[6];
    uint32_t sdst[6];
    {
        const __half* base[3] = {
            Ah + (size_t)m0 * lda, Al + (size_t)m0 * lda, Bh + (size_t)n0 * ldb };
        const uint32_t sb = smem_u32(smem);
#pragma unroll
        for (int j = 0; j < 6; j++) {
            int ci = tid + j * 256;           // 0..1535
            int mat = ci >> 9;                // 0..2
            int idx = ci & 511;
            int row = idx >> 2;               // 0..127
            int c8  = (idx & 3) * 8;          // 0,8,16,24
            int ld  = (mat < 2) ? lda : ldb;
            gsrc[j] = base[mat] + (size_t)row * ld + c8;
            sdst[j] = sb + (uint32_t)(mat * MAT_ELEMS + row * PITCH + c8) * 2u;
        }
    }

#define BG_LOAD(stage, kbase) do {                                             \
    const uint32_t _so = (uint32_t)(stage) * (STG_ELEMS * 2);                  \
    _Pragma("unroll")                                                          \
    for (int j = 0; j < 6; j++)                                                \
        asm volatile("cp.async.cg.shared.global [%0], [%1], 16;"               \
                     :: "r"(sdst[j] + _so), "l"(gsrc[j] + (kbase)) : "memory"); \
    asm volatile("cp.async.commit_group;" ::: "memory");                       \
} while (0)

    float acc[4][4][4];
#pragma unroll
    for (int mi = 0; mi < 4; mi++)
#pragma unroll
        for (int nj = 0; nj < 4; nj++)
#pragma unroll
            for (int q = 0; q < 4; q++) acc[mi][nj][q] = 0.f;

    const int r   = lane >> 2;          // 0..7
    const int cp2 = (lane & 3) * 2;     // 0,2,4,6

    BG_LOAD(0, 0);

    for (int c = 0; c < NC; c++) {
        if (c + 1 < NC) {
            BG_LOAD((c + 1) & 1, (c + 1) << 5);
            asm volatile("cp.async.wait_group 1;" ::: "memory");
        } else {
            asm volatile("cp.async.wait_group 0;" ::: "memory");
        }
        __syncthreads();

        const __half* st = smem + (c & 1) * STG_ELEMS;
        const __half* sa_h = st;
        const __half* sa_l = st + MAT_ELEMS;
        const __half* sb_h = st + 2 * MAT_ELEMS;

#pragma unroll
        for (int ks = 0; ks < 32; ks += 16) {
            uint32_t ah[4][4], al[4][4], bh[4][2];
#pragma unroll
            for (int mi = 0; mi < 4; mi++) {
                const int row = wm + mi * 16 + r;
                const __half* p0 = sa_h + row * PITCH + ks + cp2;
                const __half* p1 = sa_h + (row + 8) * PITCH + ks + cp2;
                ah[mi][0] = *(const uint32_t*)p0;
                ah[mi][1] = *(const uint32_t*)p1;
                ah[mi][2] = *(const uint32_t*)(p0 + 8);
                ah[mi][3] = *(const uint32_t*)(p1 + 8);
                const __half* q0 = sa_l + row * PITCH + ks + cp2;
                const __half* q1 = sa_l + (row + 8) * PITCH + ks + cp2;
                al[mi][0] = *(const uint32_t*)q0;
                al[mi][1] = *(const uint32_t*)q1;
                al[mi][2] = *(const uint32_t*)(q0 + 8);
                al[mi][3] = *(const uint32_t*)(q1 + 8);
            }
#pragma unroll
            for (int nj = 0; nj < 4; nj++) {
                const int row = wn + nj * 8 + r;
                const __half* p = sb_h + row * PITCH + ks + cp2;
                bh[nj][0] = *(const uint32_t*)p;
                bh[nj][1] = *(const uint32_t*)(p + 8);
            }
#pragma unroll
            for (int mi = 0; mi < 4; mi++)
#pragma unroll
                for (int nj = 0; nj < 4; nj++) {
                    mma_f16(acc[mi][nj], ah[mi], bh[nj]);
                    mma_f16(acc[mi][nj], al[mi], bh[nj]);
                }
        }
        __syncthreads();
    }

    // ---- epilogue ----
#pragma unroll
    for (int mi = 0; mi < 4; mi++) {
        const int m = m0 + wm + mi * 16 + r;
#pragma unroll
        for (int nj = 0; nj < 4; nj++) {
            const int n = n0 + wn + nj * 8 + cp2;
            const float* d = acc[mi][nj];
            if (C != nullptr) {
                float2 v0; v0.x = d[0]; v0.y = d[1];
                float2 v1; v1.x = d[2]; v1.y = d[3];
                *(float2*)(C + (size_t)m * ldc + n)       = v0;
                *(float2*)(C + (size_t)(m + 8) * ldc + n) = v1;
            } else {
#pragma unroll
                for (int half_ = 0; half_ < 2; half_++) {
                    const float v0 = d[half_ * 2], v1 = d[half_ * 2 + 1];
                    const int mm = m + half_ * 8;
                    __half h0 = __float2half_rn(v0);
                    __half h1 = __float2half_rn(v1);
                    __half2 hp; hp.x = h0; hp.y = h1;
                    __half2 lp;
                    lp.x = __float2half_rn(v0 - __half2float(h0));
                    lp.y = __float2half_rn(v1 - __half2float(h1));
                    *(__half2*)(Ch + (size_t)mm * ldc + n) = hp;
                    *(__half2*)(Cl + (size_t)mm * ldc + n) = lp;
                }
            }
        }
    }
#undef BG_LOAD
}

// ---------------------------------------------------------------------------
// fp32 -> (hi, lo) fp16 split, 2-wide vectorized.
// ---------------------------------------------------------------------------
__global__ void split2h(const float* __restrict__ src,
                        __half* __restrict__ h, __half* __restrict__ l, int n2)
{
    int i = blockIdx.x * 256 + threadIdx.x;
    if (i < n2) {
        float2 v = ((const float2*)src)[i];
        __half h0 = __float2half_rn(v.x);
        __half h1 = __float2half_rn(v.y);
        __half2 hp; hp.x = h0; hp.y = h1;
        __half2 lp;
        lp.x = __float2half_rn(v.x - __half2float(h0));
        lp.y = __float2half_rn(v.y - __half2float(h1));
        ((__half2*)h)[i] = hp;
        ((__half2*)l)[i] = lp;
    }
}

// fp32 -> fp16 round (hi only), 2-wide.
__global__ void round2h(const float* __restrict__ src, __half* __restrict__ h, int n2)
{
    int i = blockIdx.x * 256 + threadIdx.x;
    if (i < n2) {
        float2 v = ((const float2*)src)[i];
        __half2 hp; hp.x = __float2half_rn(v.x); hp.y = __float2half_rn(v.y);
        ((__half2*)h)[i] = hp;
    }
}

// ---------------------------------------------------------------------------
// fp32 SGEMM (delta GEMM, K=64).  flags bit1 = add bias[n] then softplus.
// ---------------------------------------------------------------------------
__global__ void __launch_bounds__(256)
sgemm_nt(const float* __restrict__ A, int lda,
         const float* __restrict__ B, int ldb,
         float* __restrict__ C, int ldc,
         int K, const float* __restrict__ bias, int flags)
{
    __shared__ float As[8][128];
    __shared__ float Bs[8][128];

    const int tid = threadIdx.x;
    const int m0 = blockIdx.y * 128;
    const int n0 = blockIdx.x * 128;

    const int arow = tid >> 1;
    const int acol = (tid & 1) * 4;
    const float* Aptr = A + (size_t)(m0 + arow) * lda + acol;
    const float* Bptr = B + (size_t)(n0 + arow) * ldb + acol;

    const int tx = tid & 15;
    const int ty = tid >> 4;

    float acc[8][8];
#pragma unroll
    for (int i = 0; i < 8; i++)
#pragma unroll
        for (int j = 0; j < 8; j++) acc[i][j] = 0.f;

    for (int kt = 0; kt < K; kt += 8) {
        float4 av = *(const float4*)(Aptr + kt);
        float4 bv = *(const float4*)(Bptr + kt);
        __syncthreads();
        As[acol + 0][arow] = av.x; As[acol + 1][arow] = av.y;
        As[acol + 2][arow] = av.z; As[acol + 3][arow] = av.w;
        Bs[acol + 0][arow] = bv.x; Bs[acol + 1][arow] = bv.y;
        Bs[acol + 2][arow] = bv.z; Bs[acol + 3][arow] = bv.w;
        __syncthreads();
#pragma unroll
        for (int k = 0; k < 8; k++) {
            float a[8], b[8];
            *(float4*)&a[0] = *(const float4*)&As[k][ty * 8];
            *(float4*)&a[4] = *(const float4*)&As[k][ty * 8 + 4];
            *(float4*)&b[0] = *(const float4*)&Bs[k][tx * 8];
            *(float4*)&b[4] = *(const float4*)&Bs[k][tx * 8 + 4];
#pragma unroll
            for (int i = 0; i < 8; i++)
#pragma unroll
                for (int j = 0; j < 8; j++)
                    acc[i][j] += a[i] * b[j];
        }
    }

#pragma unroll
    for (int i = 0; i < 8; i++) {
        const int m = m0 + ty * 8 + i;
        float* crow = C + (size_t)m * ldc + n0 + tx * 8;
#pragma unroll
        for (int j = 0; j < 8; j++) {
            float v = acc[i][j];
            if (flags & 2) {
                v += bias[n0 + tx * 8 + j];
                v = (v > 20.f) ? v : log1pf(__expf(v));
            }
            acc[i][j] = v;
        }
        *(float4*)crow       = *(float4*)&acc[i][0];
        *(float4*)(crow + 4) = *(float4*)&acc[i][4];
    }
}

// ---------------------------------------------------------------------------
// Skinny GEMM for x_proj: M=2048, N=96, K=2048, split-K over gridDim.y=8.
// ---------------------------------------------------------------------------
__global__ void __launch_bounds__(256)
sgemm_skinny96(const float* __restrict__ A, int lda,
               const float* __restrict__ B, int ldb,
               float* __restrict__ Cpart, int K)
{
    __shared__ float As[16][128];
    __shared__ float Bs[16][96];

    const int tid = threadIdx.x;
    const int m0 = blockIdx.x * 128;
    const int kchunk = K >> 3;
    const int kbase = blockIdx.y * kchunk;
    float* C = Cpart + (size_t)blockIdx.y * (ML * DBLW);

    const int tx = tid & 15;
    const int ty = tid >> 4;

    float acc[8][6];
#pragma unroll
    for (int i = 0; i < 8; i++)
#pragma unroll
        for (int j = 0; j < 6; j++) acc[i][j] = 0.f;

    for (int kt = 0; kt < kchunk; kt += 16) {
        __syncthreads();
#pragma unroll
        for (int f = 0; f < 2; f++) {
            int fid = tid + f * 256;
            int row = fid >> 2, c4 = (fid & 3) * 4;
            float4 v = *(const float4*)(A + (size_t)(m0 + row) * lda + kbase + kt + c4);
            As[c4 + 0][row] = v.x; As[c4 + 1][row] = v.y;
            As[c4 + 2][row] = v.z; As[c4 + 3][row] = v.w;
        }
#pragma unroll
        for (int f = 0; f < 2; f++) {
            int fid = tid + f * 256;
            if (fid < 384) {
                int row = fid >> 2, c4 = (fid & 3) * 4;
                float4 v = *(const float4*)(B + (size_t)row * ldb + kbase + kt + c4);
                Bs[c4 + 0][row] = v.x; Bs[c4 + 1][row] = v.y;
                Bs[c4 + 2][row] = v.z; Bs[c4 + 3][row] = v.w;
            }
        }
        __syncthreads();
#pragma unroll
        for (int k = 0; k < 16; k++) {
            float a[8], b[6];
            *(float4*)&a[0] = *(const float4*)&As[k][ty * 8];
            *(float4*)&a[4] = *(const float4*)&As[k][ty * 8 + 4];
#pragma unroll
            for (int j = 0; j < 6; j++) b[j] = Bs[k][tx * 6 + j];
#pragma unroll
            for (int i = 0; i < 8; i++)
#pragma unroll
                for (int j = 0; j < 6; j++)
                    acc[i][j] += a[i] * b[j];
        }
    }
#pragma unroll
    for (int i = 0; i < 8; i++)
#pragma unroll
        for (int j = 0; j < 6; j++)
            C[(size_t)(m0 + ty * 8 + i) * DBLW + tx * 6 + j] = acc[i][j];
}

__global__ void reduce_dbl()
{
    int i = blockIdx.x * 256 + threadIdx.x;
    if (i < 2 * ML * DBLW) {
        int d = i / (ML * DBLW);
        int j = i - d * (ML * DBLW);
        float s = 0.f;
#pragma unroll
        for (int p = 0; p < 8; p++) s += g_dblp[d][p][j];
        g_dbl[d][j] = s;
    }
}

// ---------------------------------------------------------------------------
// Depthwise conv (d_conv=4) + SiLU.
// ---------------------------------------------------------------------------
__global__ void conv_silu_kernel(const float* __restrict__ cwf, const float* __restrict__ cbf,
                                 const float* __restrict__ cwb, const float* __restrict__ cbb)
{
    const int dir = blockIdx.y;
    const int idx = blockIdx.x * 256 + threadIdx.x;
    const int e = idx & (DINNER - 1);
    const int bl = idx >> 11;
    const int l = bl & (SEQ - 1);

    const float* xz = g_xz[dir];
    const float* cw = dir ? cwb : cwf;
    const float* cb = dir ? cbb : cbf;

    float s = cb[e];
    const float* base = xz + (size_t)(bl - l) * (2 * DINNER) + e;
#pragma unroll
    for (int k = 0; k < 4; k++) {
        int ls = dir ? (l + 3 - k) : (l + k - 3);
        if (ls >= 0 && ls < SEQ)
            s += cw[e * 4 + k] * base[(size_t)ls * (2 * DINNER)];
    }
    g_xc[dir][idx] = s * (1.0f / (1.0f + __expf(-s)));
}

// ---------------------------------------------------------------------------
// Selective scan + gating; epilogue writes y as fp16 hi/lo split.
// ---------------------------------------------------------------------------
__global__ void __launch_bounds__(128)
scan_kernel(const float* __restrict__ alogf, const float* __restrict__ Df,
            const float* __restrict__ alogb, const float* __restrict__ Db)
{
    const int dir = blockIdx.y;
    const int lane16 = threadIdx.x & 15;
    const int ch = (blockIdx.x * 128 + threadIdx.x) >> 4;
    const int b = ch >> 11;
    const int e = ch & (DINNER - 1);

    const float* alog = dir ? alogb : alogf;
    const float* Dvp  = dir ? Db : Df;

    const float A  = -__expf(alog[e * DSTATE + lane16]);
    const float Dv = Dvp[e];

    const float* delta = g_delta[dir];
    const float* xc    = g_xc[dir];
    const float* dbl   = g_dbl[dir];
    const float* zb    = g_xz[dir];
    __half* yh         = g_yh[dir];
    __half* yl         = g_yl[dir];

    float h = 0.f;
    int l = dir ? (SEQ - 1) : 0;
    const int lstep = dir ? -1 : 1;

#pragma unroll 2
    for (int t = 0; t < SEQ; t++, l += lstep) {
        const int bl = b * SEQ + l;
        const float dl  = delta[(size_t)bl * DINNER + e];
        const float xcv = xc[(size_t)bl * DINNER + e];
        const float Bv  = dbl[bl * DBLW + DTRANK + lane16];
        const float Cv  = dbl[bl * DBLW + DTRANK + DSTATE + lane16];

        const float dA = __expf(dl * A);
        h = dA * h + (dl * xcv) * Bv;
        float p = h * Cv;
        p += __shfl_xor_sync(0xffffffffu, p, 1);
        p += __shfl_xor_sync(0xffffffffu, p, 2);
        p += __shfl_xor_sync(0xffffffffu, p, 4);
        p += __shfl_xor_sync(0xffffffffu, p, 8);
        if (lane16 == 0) {
            const float zv = zb[(size_t)bl * (2 * DINNER) + DINNER + e];
            const float gate = zv * (1.0f / (1.0f + __expf(-zv)));
            const float yv = (p + xcv * Dv) * gate;
            __half hv = __float2half_rn(yv);
            yh[(size_t)bl * DINNER + e] = hv;
            yl[(size_t)bl * DINNER + e] = __float2half_rn(yv - __half2float(hv));
        }
    }
}

// ---------------------------------------------------------------------------
extern "C" void kernel_launch(void* const* d_in, const int* in_sizes, int n_in,
                              void* d_out, int out_size)
{
    const float* x = (const float*)d_in[0];
    const float* ip[2]   = {(const float*)d_in[1],  (const float*)d_in[10]};
    const float* cw[2]   = {(const float*)d_in[2],  (const float*)d_in[11]};
    const float* cb[2]   = {(const float*)d_in[3],  (const float*)d_in[12]};
    const float* xpj[2]  = {(const float*)d_in[4],  (const float*)d_in[13]};
    const float* dtw[2]  = {(const float*)d_in[5],  (const float*)d_in[14]};
    const float* dtb[2]  = {(const float*)d_in[6],  (const float*)d_in[15]};
    const float* alog[2] = {(const float*)d_in[7],  (const float*)d_in[16]};
    const float* Dp[2]   = {(const float*)d_in[8],  (const float*)d_in[17]};
    const float* op[2]   = {(const float*)d_in[9],  (const float*)d_in[18]};
    const float* mw = (const float*)d_in[19];

    float *xz, *xc, *dblp, *dbl, *delta;
    __half *xh, *xl, *iph, *oph, *mwh, *yh, *yl, *odh, *odl;
    cudaGetSymbolAddress((void**)&xz,    g_xz);
    cudaGetSymbolAddress((void**)&xc,    g_xc);
    cudaGetSymbolAddress((void**)&dblp,  g_dblp);
    cudaGetSymbolAddress((void**)&dbl,   g_dbl);
    cudaGetSymbolAddress((void**)&delta, g_delta);
    cudaGetSymbolAddress((void**)&xh,    g_xh);
    cudaGetSymbolAddress((void**)&xl,    g_xl);
    cudaGetSymbolAddress((void**)&iph,   g_iph);
    cudaGetSymbolAddress((void**)&oph,   g_oph);
    cudaGetSymbolAddress((void**)&mwh,   g_mwh);
    cudaGetSymbolAddress((void**)&yh,    g_yh);
    cudaGetSymbolAddress((void**)&yl,    g_yl);
    cudaGetSymbolAddress((void**)&odh,   g_odh);
    cudaGetSymbolAddress((void**)&odl,   g_odl);

    cudaFuncSetAttribute(bgemm, cudaFuncAttributeMaxDynamicSharedMemorySize, BG_SMEM_BYTES);

    const size_t SZ_XZ  = (size_t)ML * 2 * DINNER;
    const size_t SZ_E   = (size_t)ML * DINNER;
    const size_t SZ_DBL = (size_t)ML * DBLW;
    const size_t SZ_IP  = (size_t)2 * DINNER * DMODEL;
    const size_t SZ_OP  = (size_t)DMODEL * DINNER;

    // 0) fp16 conversions: x split (A-side), weights round-only (B-side)
    {
        int n2;
        n2 = ML * DMODEL / 2;
        split2h<<<(n2 + 255) / 256, 256>>>(x, xh, xl, n2);
        n2 = (int)(SZ_IP / 2);
        for (int d = 0; d < 2; d++)
            round2h<<<(n2 + 255) / 256, 256>>>(ip[d], iph + d * SZ_IP, n2);
        n2 = (int)(SZ_OP / 2);
        for (int d = 0; d < 2; d++)
            round2h<<<(n2 + 255) / 256, 256>>>(op[d], oph + d * SZ_OP, n2);
        n2 = DMODEL * 2 * DMODEL / 2;
        round2h<<<(n2 + 255) / 256, 256>>>(mw, mwh, n2);
    }

    // 1) input projections (tensor cores): xz = x @ in_proj^T   (2048 x 4096)
    for (int d = 0; d < 2; d++)
        bgemm<<<dim3(2 * DINNER / 128, ML / 128), 256, BG_SMEM_BYTES>>>(
            xh, xl, DMODEL, iph + d * SZ_IP, DMODEL,
            xz + d * SZ_XZ, nullptr, nullptr, 2 * DINNER, DMODEL);

    // 2) depthwise conv + silu
    conv_silu_kernel<<<dim3(ML * DINNER / 256, 2), 256>>>(cw[0], cb[0], cw[1], cb[1]);

    // 3) x_proj (skinny, split-K=8) + reduce
    for (int d = 0; d < 2; d++)
        sgemm_skinny96<<<dim3(ML / 128, 8), 256>>>(
            xc + d * SZ_E, DINNER, xpj[d], DINNER,
            dblp + (size_t)d * 8 * SZ_DBL, DINNER);
    reduce_dbl<<<(2 * ML * DBLW + 255) / 256, 256>>>();

    // 4) delta = softplus(dt @ dt_w^T + dt_b)   (fp32, K=64)
    for (int d = 0; d < 2; d++)
        sgemm_nt<<<dim3(DINNER / 128, ML / 128), 256>>>(
            dbl + d * SZ_DBL, DBLW, dtw[d], DTRANK,
            delta + d * SZ_E, DINNER, DTRANK, dtb[d], 2);

    // 5) selective scan + gating (writes y as fp16 hi/lo)
    scan_kernel<<<dim3(BSZ * DINNER * DSTATE / 128, 2), 128>>>(
        alog[0], Dp[0], alog[1], Dp[1]);

    // 6) output projections (tensor cores): od[:, d*1024:(d+1)*1024] = y @ op^T
    //    written as fp16 hi/lo into the concatenated od buffer (ldc = 2048).
    for (int d = 0; d < 2; d++)
        bgemm<<<dim3(DMODEL / 128, ML / 128), 256, BG_SMEM_BYTES>>>(
            yh + d * SZ_E, yl + d * SZ_E, DINNER,
            oph + d * SZ_OP, DINNER,
            nullptr, odh + d * DMODEL, odl + d * DMODEL, 2 * DMODEL, DINNER);

    // 7) merge (tensor cores): out = odcat @ merge_w^T   (K = 2048, single GEMM)
    bgemm<<<dim3(DMODEL / 128, ML / 128), 256, BG_SMEM_BYTES>>>(
        odh, odl, 2 * DMODEL, mwh, 2 * DMODEL,
        (float*)d_out, nullptr, nullptr, DMODEL, 2 * DMODEL);
}

// round 14
// speedup vs baseline: 1.2731x; 1.0166x over previous
#include <cuda_runtime.h>
#include <cuda_fp16.h>
#include <cuda_bf16.h>
#include <cstdint>

// ---------------------------------------------------------------------------
// BiMamba: B=2, L=1024, d_model=1024, d_inner=2048, d_state=16, d_conv=4,
// dt_rank=64.
//
// Big GEMMs (in_proj / out_proj / merge) on tensor cores via mma.sync fp16
// 2-product split precision:  a = ah + al (both fp16, 22 mantissa bits),
// b ~= bh (fp16 round, rel err 2^-12);  C = ah*bh + al*bh = a*bh.
// fp32 accumulators.  bgemm v3: R12 config + ldmatrix.x4 fragment loads
// (shared-op count per warp-chunk 80 -> 20; restores MMA-bound operation).
// ---------------------------------------------------------------------------

#define BSZ 2
#define SEQ 1024
#define DMODEL 1024
#define DINNER 2048
#define DSTATE 16
#define DTRANK 64
#define ML (BSZ * SEQ)          // 2048 rows
#define DBLW 96                 // dt_rank + 2*d_state

// ------------------------------ scratch (device globals) -------------------
__device__ __align__(128) float g_xz   [2][ML * 2 * DINNER];
__device__ __align__(128) float g_xc   [2][ML * DINNER];
__device__ __align__(128) float g_dblp [2][8][ML * DBLW];
__device__ __align__(128) float g_dbl  [2][ML * DBLW];
__device__ __align__(128) float g_delta[2][ML * DINNER];

__device__ __align__(128) __half g_xh [ML * DMODEL];
__device__ __align__(128) __half g_xl [ML * DMODEL];
__device__ __align__(128) __half g_iph[2][2 * DINNER * DMODEL];   // B-side: hi only
__device__ __align__(128) __half g_oph[2][DMODEL * DINNER];
__device__ __align__(128) __half g_mwh[DMODEL * 2 * DMODEL];
__device__ __align__(128) __half g_yh [2][ML * DINNER];
__device__ __align__(128) __half g_yl [2][ML * DINNER];
__device__ __align__(128) __half g_odh[ML * 2 * DMODEL];          // [f | b] cols
__device__ __align__(128) __half g_odl[ML * 2 * DMODEL];

// ------------------------------ helpers ------------------------------------
__device__ __forceinline__ uint32_t smem_u32(const void* p) {
    uint32_t a;
    asm("{ .reg .u64 t; cvta.to.shared.u64 t, %1; cvt.u32.u64 %0, t; }"
        : "=r"(a) : "l"(p));
    return a;
}

__device__ __forceinline__ void mma_f16(float* d, const uint32_t* a, const uint32_t* b) {
    asm volatile(
        "mma.sync.aligned.m16n8k16.row.col.f32.f16.f16.f32 "
        "{%0,%1,%2,%3}, {%4,%5,%6,%7}, {%8,%9}, {%0,%1,%2,%3};"
        : "+f"(d[0]), "+f"(d[1]), "+f"(d[2]), "+f"(d[3])
        : "r"(a[0]), "r"(a[1]), "r"(a[2]), "r"(a[3]), "r"(b[0]), "r"(b[1]));
}

__device__ __forceinline__ void ldsm4(uint32_t* r, uint32_t addr) {
    asm volatile("ldmatrix.sync.aligned.m8n8.x4.shared.b16 {%0,%1,%2,%3}, [%4];"
                 : "=r"(r[0]), "=r"(r[1]), "=r"(r[2]), "=r"(r[3]) : "r"(addr));
}

// ---------------------------------------------------------------------------
// fp16 2-product mma.sync GEMM:  C[m,n] = sum_k A[m,k]*B[n,k]  (NT, row-major)
// A given as fp16 (hi,lo) pair; B as fp16 hi.  CTA tile 128x128, K-chunk 32,
// 256 threads (8 warps, 64x32 warp tiles), 2-stage cp.async, ldmatrix.x4.
// Output: fp32 C, or fp16 hi/lo split (Ch/Cl).
// Requires M%128==0, N%128==0, K%32==0 (true for all call sites).
// ---------------------------------------------------------------------------
#define PITCH 40                              // fp16 elems per smem row (pad)
#define MAT_ELEMS (128 * PITCH)               // 5120 per matrix
#define STG_ELEMS (3 * MAT_ELEMS)             // Ah | Al | Bh
#define BG_SMEM_BYTES (2 * STG_ELEMS * 2)     // 61440 bytes

__global__ void __launch_bounds__(256, 2)
bgemm(const __half* __restrict__ Ah, const __half* __restrict__ Al, int lda,
      const __half* __restrict__ Bh, int ldb,
      float* __restrict__ C, __half* __restrict__ Ch, __half* __restrict__ Cl,
      int ldc, int K)
{
    extern __shared__ __align__(16) __half smem[];   // 2 stages

    const int tid  = threadIdx.x;
    const int lane = tid & 31;
    const int wid  = tid >> 5;
    const int wm   = (wid & 1) * 64;      // warp m-offset within CTA tile
    const int wn   = (wid >> 1) * 32;     // warp n-offset
    const int m0   = blockIdx.y * 128;
    const int n0   = blockIdx.x * 128;
    const int NC   = K >> 5;              // chunks of 32
    const uint32_t sb = smem_u32(smem);

    // ---- fixed per-thread load assignment: 6x cp.async.cg (16B each) ----
    const __half* gsrc[6];
    uint32_t sdst[6];
    {
        const __half* base[3] = {
            Ah + (size_t)m0 * lda, Al + (size_t)m0 * lda, Bh + (size_t)n0 * ldb };
#pragma unroll
        for (int j = 0; j < 6; j++) {
            int ci = tid + j * 256;           // 0..1535
            int mat = ci >> 9;                // 0..2
            int idx = ci & 511;
            int row = idx >> 2;               // 0..127
            int c8  = (idx & 3) * 8;          // 0,8,16,24
            int ld  = (mat < 2) ? lda : ldb;
            gsrc[j] = base[mat] + (size_t)row * ld + c8;
            sdst[j] = sb + (uint32_t)(mat * MAT_ELEMS + row * PITCH + c8) * 2u;
        }
    }

#define BG_LOAD(stage, kbase) do {                                             \
    const uint32_t _so = (uint32_t)(stage) * (STG_ELEMS * 2);                  \
    _Pragma("unroll")                                                          \
    for (int j = 0; j < 6; j++)                                                \
        asm volatile("cp.async.cg.shared.global [%0], [%1], 16;"               \
                     :: "r"(sdst[j] + _so), "l"(gsrc[j] + (kbase)) : "memory"); \
    asm volatile("cp.async.commit_group;" ::: "memory");                       \
} while (0)

    float acc[4][4][4];
#pragma unroll
    for (int mi = 0; mi < 4; mi++)
#pragma unroll
        for (int nj = 0; nj < 4; nj++)
#pragma unroll
            for (int q = 0; q < 4; q++) acc[mi][nj][q] = 0.f;

    // ldmatrix per-lane element offsets (proven in R9)
    const uint32_t aoff = (uint32_t)((((lane & 7) + ((lane >> 3) & 1) * 8) * PITCH) +
                                     ((lane >> 4) * 8));
    const uint32_t boff = (uint32_t)((((lane & 7) + (lane >> 4) * 8) * PITCH) +
                                     (((lane >> 3) & 1) * 8));

    BG_LOAD(0, 0);

    for (int c = 0; c < NC; c++) {
        if (c + 1 < NC) {
            BG_LOAD((c + 1) & 1, (c + 1) << 5);
            asm volatile("cp.async.wait_group 1;" ::: "memory");
        } else {
            asm volatile("cp.async.wait_group 0;" ::: "memory");
        }
        __syncthreads();

        const uint32_t st  = sb + (uint32_t)(c & 1) * (STG_ELEMS * 2);
        const uint32_t sAh = st;
        const uint32_t sAl = st + MAT_ELEMS * 2;
        const uint32_t sBh = st + 2 * MAT_ELEMS * 2;

#pragma unroll
        for (int ks = 0; ks < 32; ks += 16) {
            uint32_t ah[4][4], al[4][4], bh[2][4];
#pragma unroll
            for (int mi = 0; mi < 4; mi++) {
                const uint32_t rbase = (uint32_t)((wm + mi * 16) * PITCH + ks);
                ldsm4(ah[mi], sAh + (rbase + aoff) * 2u);
                ldsm4(al[mi], sAl + (rbase + aoff) * 2u);
            }
#pragma unroll
            for (int p = 0; p < 2; p++) {
                const uint32_t rbase = (uint32_t)((wn + p * 16) * PITCH + ks);
                ldsm4(bh[p], sBh + (rbase + boff) * 2u);
            }
#pragma unroll
            for (int mi = 0; mi < 4; mi++)
#pragma unroll
                for (int nj = 0; nj < 4; nj++) {
                    const uint32_t* bp = &bh[nj >> 1][(nj & 1) * 2];
                    mma_f16(acc[mi][nj], ah[mi], bp);
                    mma_f16(acc[mi][nj], al[mi], bp);
                }
        }
        __syncthreads();
    }

    // ---- epilogue ----
    const int r   = lane >> 2;          // 0..7
    const int cp2 = (lane & 3) * 2;     // 0,2,4,6
#pragma unroll
    for (int mi = 0; mi < 4; mi++) {
        const int m = m0 + wm + mi * 16 + r;
#pragma unroll
        for (int nj = 0; nj < 4; nj++) {
            const int n = n0 + wn + nj * 8 + cp2;
            const float* d = acc[mi][nj];
            if (C != nullptr) {
                float2 v0; v0.x = d[0]; v0.y = d[1];
                float2 v1; v1.x = d[2]; v1.y = d[3];
                *(float2*)(C + (size_t)m * ldc + n)       = v0;
                *(float2*)(C + (size_t)(m + 8) * ldc + n) = v1;
            } else {
#pragma unroll
                for (int half_ = 0; half_ < 2; half_++) {
                    const float v0 = d[half_ * 2], v1 = d[half_ * 2 + 1];
                    const int mm = m + half_ * 8;
                    __half h0 = __float2half_rn(v0);
                    __half h1 = __float2half_rn(v1);
                    __half2 hp; hp.x = h0; hp.y = h1;
                    __half2 lp;
                    lp.x = __float2half_rn(v0 - __half2float(h0));
                    lp.y = __float2half_rn(v1 - __half2float(h1));
                    *(__half2*)(Ch + (size_t)mm * ldc + n) = hp;
                    *(__half2*)(Cl + (size_t)mm * ldc + n) = lp;
                }
            }
        }
    }
#undef BG_LOAD
}

// ---------------------------------------------------------------------------
// fp32 -> (hi, lo) fp16 split, 2-wide vectorized.
// ---------------------------------------------------------------------------
__global__ void split2h(const float* __restrict__ src,
                        __half* __restrict__ h, __half* __restrict__ l, int n2)
{
    int i = blockIdx.x * 256 + threadIdx.x;
    if (i < n2) {
        float2 v = ((const float2*)src)[i];
        __half h0 = __float2half_rn(v.x);
        __half h1 = __float2half_rn(v.y);
        __half2 hp; hp.x = h0; hp.y = h1;
        __half2 lp;
        lp.x = __float2half_rn(v.x - __half2float(h0));
        lp.y = __float2half_rn(v.y - __half2float(h1));
        ((__half2*)h)[i] = hp;
        ((__half2*)l)[i] = lp;
    }
}

// fp32 -> fp16 round (hi only), 2-wide.
__global__ void round2h(const float* __restrict__ src, __half* __restrict__ h, int n2)
{
    int i = blockIdx.x * 256 + threadIdx.x;
    if (i < n2) {
        float2 v = ((const float2*)src)[i];
        __half2 hp; hp.x = __float2half_rn(v.x); hp.y = __float2half_rn(v.y);
        ((__half2*)h)[i] = hp;
    }
}

// ---------------------------------------------------------------------------
// fp32 SGEMM (delta GEMM, K=64).  flags bit1 = add bias[n] then softplus.
// ---------------------------------------------------------------------------
__global__ void __launch_bounds__(256)
sgemm_nt(const float* __restrict__ A, int lda,
         const float* __restrict__ B, int ldb,
         float* __restrict__ C, int ldc,
         int K, const float* __restrict__ bias, int flags)
{
    __shared__ float As[8][128];
    __shared__ float Bs[8][128];

    const int tid = threadIdx.x;
    const int m0 = blockIdx.y * 128;
    const int n0 = blockIdx.x * 128;

    const int arow = tid >> 1;
    const int acol = (tid & 1) * 4;
    const float* Aptr = A + (size_t)(m0 + arow) * lda + acol;
    const float* Bptr = B + (size_t)(n0 + arow) * ldb + acol;

    const int tx = tid & 15;
    const int ty = tid >> 4;

    float acc[8][8];
#pragma unroll
    for (int i = 0; i < 8; i++)
#pragma unroll
        for (int j = 0; j < 8; j++) acc[i][j] = 0.f;

    for (int kt = 0; kt < K; kt += 8) {
        float4 av = *(const float4*)(Aptr + kt);
        float4 bv = *(const float4*)(Bptr + kt);
        __syncthreads();
        As[acol + 0][arow] = av.x; As[acol + 1][arow] = av.y;
        As[acol + 2][arow] = av.z; As[acol + 3][arow] = av.w;
        Bs[acol + 0][arow] = bv.x; Bs[acol + 1][arow] = bv.y;
        Bs[acol + 2][arow] = bv.z; Bs[acol + 3][arow] = bv.w;
        __syncthreads();
#pragma unroll
        for (int k = 0; k < 8; k++) {
            float a[8], b[8];
            *(float4*)&a[0] = *(const float4*)&As[k][ty * 8];
            *(float4*)&a[4] = *(const float4*)&As[k][ty * 8 + 4];
            *(float4*)&b[0] = *(const float4*)&Bs[k][tx * 8];
            *(float4*)&b[4] = *(const float4*)&Bs[k][tx * 8 + 4];
#pragma unroll
            for (int i = 0; i < 8; i++)
#pragma unroll
                for (int j = 0; j < 8; j++)
                    acc[i][j] += a[i] * b[j];
        }
    }

#pragma unroll
    for (int i = 0; i < 8; i++) {
        const int m = m0 + ty * 8 + i;
        float* crow = C + (size_t)m * ldc + n0 + tx * 8;
#pragma unroll
        for (int j = 0; j < 8; j++) {
            float v = acc[i][j];
            if (flags & 2) {
                v += bias[n0 + tx * 8 + j];
                v = (v > 20.f) ? v : log1pf(__expf(v));
            }
            acc[i][j] = v;
        }
        *(float4*)crow       = *(float4*)&acc[i][0];
        *(float4*)(crow + 4) = *(float4*)&acc[i][4];
    }
}

// ---------------------------------------------------------------------------
// Skinny GEMM for x_proj: M=2048, N=96, K=2048, split-K over gridDim.y=8.
// ---------------------------------------------------------------------------
__global__ void __launch_bounds__(256)
sgemm_skinny96(const float* __restrict__ A, int lda,
               const float* __restrict__ B, int ldb,
               float* __restrict__ Cpart, int K)
{
    __shared__ float As[16][128];
    __shared__ float Bs[16][96];

    const int tid = threadIdx.x;
    const int m0 = blockIdx.x * 128;
    const int kchunk = K >> 3;
    const int kbase = blockIdx.y * kchunk;
    float* C = Cpart + (size_t)blockIdx.y * (ML * DBLW);

    const int tx = tid & 15;
    const int ty = tid >> 4;

    float acc[8][6];
#pragma unroll
    for (int i = 0; i < 8; i++)
#pragma unroll
        for (int j = 0; j < 6; j++) acc[i][j] = 0.f;

    for (int kt = 0; kt < kchunk; kt += 16) {
        __syncthreads();
#pragma unroll
        for (int f = 0; f < 2; f++) {
            int fid = tid + f * 256;
            int row = fid >> 2, c4 = (fid & 3) * 4;
            float4 v = *(const float4*)(A + (size_t)(m0 + row) * lda + kbase + kt + c4);
            As[c4 + 0][row] = v.x; As[c4 + 1][row] = v.y;
            As[c4 + 2][row] = v.z; As[c4 + 3][row] = v.w;
        }
#pragma unroll
        for (int f = 0; f < 2; f++) {
            int fid = tid + f * 256;
            if (fid < 384) {
                int row = fid >> 2, c4 = (fid & 3) * 4;
                float4 v = *(const float4*)(B + (size_t)row * ldb + kbase + kt + c4);
                Bs[c4 + 0][row] = v.x; Bs[c4 + 1][row] = v.y;
                Bs[c4 + 2][row] = v.z; Bs[c4 + 3][row] = v.w;
            }
        }
        __syncthreads();
#pragma unroll
        for (int k = 0; k < 16; k++) {
            float a[8], b[6];
            *(float4*)&a[0] = *(const float4*)&As[k][ty * 8];
            *(float4*)&a[4] = *(const float4*)&As[k][ty * 8 + 4];
#pragma unroll
            for (int j = 0; j < 6; j++) b[j] = Bs[k][tx * 6 + j];
#pragma unroll
            for (int i = 0; i < 8; i++)
#pragma unroll
                for (int j = 0; j < 6; j++)
                    acc[i][j] += a[i] * b[j];
        }
    }
#pragma unroll
    for (int i = 0; i < 8; i++)
#pragma unroll
        for (int j = 0; j < 6; j++)
            C[(size_t)(m0 + ty * 8 + i) * DBLW + tx * 6 + j] = acc[i][j];
}

__global__ void reduce_dbl()
{
    int i = blockIdx.x * 256 + threadIdx.x;
    if (i < 2 * ML * DBLW) {
        int d = i / (ML * DBLW);
        int j = i - d * (ML * DBLW);
        float s = 0.f;
#pragma unroll
        for (int p = 0; p < 8; p++) s += g_dblp[d][p][j];
        g_dbl[d][j] = s;
    }
}

// ---------------------------------------------------------------------------
// Depthwise conv (d_conv=4) + SiLU.
// ---------------------------------------------------------------------------
__global__ void conv_silu_kernel(const float* __restrict__ cwf, const float* __restrict__ cbf,
                                 const float* __restrict__ cwb, const float* __restrict__ cbb)
{
    const int dir = blockIdx.y;
    const int idx = blockIdx.x * 256 + threadIdx.x;
    const int e = idx & (DINNER - 1);
    const int bl = idx >> 11;
    const int l = bl & (SEQ - 1);

    const float* xz = g_xz[dir];
    const float* cw = dir ? cwb : cwf;
    const float* cb = dir ? cbb : cbf;

    float s = cb[e];
    const float* base = xz + (size_t)(bl - l) * (2 * DINNER) + e;
#pragma unroll
    for (int k = 0; k < 4; k++) {
        int ls = dir ? (l + 3 - k) : (l + k - 3);
        if (ls >= 0 && ls < SEQ)
            s += cw[e * 4 + k] * base[(size_t)ls * (2 * DINNER)];
    }
    g_xc[dir][idx] = s * (1.0f / (1.0f + __expf(-s)));
}

// ---------------------------------------------------------------------------
// Selective scan + gating; epilogue writes y as fp16 hi/lo split.
// ---------------------------------------------------------------------------
__global__ void __launch_bounds__(128)
scan_kernel(const float* __restrict__ alogf, const float* __restrict__ Df,
            const float* __restrict__ alogb, const float* __restrict__ Db)
{
    const int dir = blockIdx.y;
    const int lane16 = threadIdx.x & 15;
    const int ch = (blockIdx.x * 128 + threadIdx.x) >> 4;
    const int b = ch >> 11;
    const int e = ch & (DINNER - 1);

    const float* alog = dir ? alogb : alogf;
    const float* Dvp  = dir ? Db : Df;

    const float A  = -__expf(alog[e * DSTATE + lane16]);
    const float Dv = Dvp[e];

    const float* delta = g_delta[dir];
    const float* xc    = g_xc[dir];
    const float* dbl   = g_dbl[dir];
    const float* zb    = g_xz[dir];
    __half* yh         = g_yh[dir];
    __half* yl         = g_yl[dir];

    float h = 0.f;
    int l = dir ? (SEQ - 1) : 0;
    const int lstep = dir ? -1 : 1;

#pragma unroll 2
    for (int t = 0; t < SEQ; t++, l += lstep) {
        const int bl = b * SEQ + l;
        const float dl  = delta[(size_t)bl * DINNER + e];
        const float xcv = xc[(size_t)bl * DINNER + e];
        const float Bv  = dbl[bl * DBLW + DTRANK + lane16];
        const float Cv  = dbl[bl * DBLW + DTRANK + DSTATE + lane16];

        const float dA = __expf(dl * A);
        h = dA * h + (dl * xcv) * Bv;
        float p = h * Cv;
        p += __shfl_xor_sync(0xffffffffu, p, 1);
        p += __shfl_xor_sync(0xffffffffu, p, 2);
        p += __shfl_xor_sync(0xffffffffu, p, 4);
        p += __shfl_xor_sync(0xffffffffu, p, 8);
        if (lane16 == 0) {
            const float zv = zb[(size_t)bl * (2 * DINNER) + DINNER + e];
            const float gate = zv * (1.0f / (1.0f + __expf(-zv)));
            const float yv = (p + xcv * Dv) * gate;
            __half hv = __float2half_rn(yv);
            yh[(size_t)bl * DINNER + e] = hv;
            yl[(size_t)bl * DINNER + e] = __float2half_rn(yv - __half2float(hv));
        }
    }
}

// ---------------------------------------------------------------------------
extern "C" void kernel_launch(void* const* d_in, const int* in_sizes, int n_in,
                              void* d_out, int out_size)
{
    const float* x = (const float*)d_in[0];
    const float* ip[2]   = {(const float*)d_in[1],  (const float*)d_in[10]};
    const float* cw[2]   = {(const float*)d_in[2],  (const float*)d_in[11]};
    const float* cb[2]   = {(const float*)d_in[3],  (const float*)d_in[12]};
    const float* xpj[2]  = {(const float*)d_in[4],  (const float*)d_in[13]};
    const float* dtw[2]  = {(const float*)d_in[5],  (const float*)d_in[14]};
    const float* dtb[2]  = {(const float*)d_in[6],  (const float*)d_in[15]};
    const float* alog[2] = {(const float*)d_in[7],  (const float*)d_in[16]};
    const float* Dp[2]   = {(const float*)d_in[8],  (const float*)d_in[17]};
    const float* op[2]   = {(const float*)d_in[9],  (const float*)d_in[18]};
    const float* mw = (const float*)d_in[19];

    float *xz, *xc, *dblp, *dbl, *delta;
    __half *xh, *xl, *iph, *oph, *mwh, *yh, *yl, *odh, *odl;
    cudaGetSymbolAddress((void**)&xz,    g_xz);
    cudaGetSymbolAddress((void**)&xc,    g_xc);
    cudaGetSymbolAddress((void**)&dblp,  g_dblp);
    cudaGetSymbolAddress((void**)&dbl,   g_dbl);
    cudaGetSymbolAddress((void**)&delta, g_delta);
    cudaGetSymbolAddress((void**)&xh,    g_xh);
    cudaGetSymbolAddress((void**)&xl,    g_xl);
    cudaGetSymbolAddress((void**)&iph,   g_iph);
    cudaGetSymbolAddress((void**)&oph,   g_oph);
    cudaGetSymbolAddress((void**)&mwh,   g_mwh);
    cudaGetSymbolAddress((void**)&yh,    g_yh);
    cudaGetSymbolAddress((void**)&yl,    g_yl);
    cudaGetSymbolAddress((void**)&odh,   g_odh);
    cudaGetSymbolAddress((void**)&odl,   g_odl);

    cudaFuncSetAttribute(bgemm, cudaFuncAttributeMaxDynamicSharedMemorySize, BG_SMEM_BYTES);

    const size_t SZ_XZ  = (size_t)ML * 2 * DINNER;
    const size_t SZ_E   = (size_t)ML * DINNER;
    const size_t SZ_DBL = (size_t)ML * DBLW;
    const size_t SZ_IP  = (size_t)2 * DINNER * DMODEL;
    const size_t SZ_OP  = (size_t)DMODEL * DINNER;

    // 0) fp16 conversions: x split (A-side), weights round-only (B-side)
    {
        int n2;
        n2 = ML * DMODEL / 2;
        split2h<<<(n2 + 255) / 256, 256>>>(x, xh, xl, n2);
        n2 = (int)(SZ_IP / 2);
        for (int d = 0; d < 2; d++)
            round2h<<<(n2 + 255) / 256, 256>>>(ip[d], iph + d * SZ_IP, n2);
        n2 = (int)(SZ_OP / 2);
        for (int d = 0; d < 2; d++)
            round2h<<<(n2 + 255) / 256, 256>>>(op[d], oph + d * SZ_OP, n2);
        n2 = DMODEL * 2 * DMODEL / 2;
        round2h<<<(n2 + 255) / 256, 256>>>(mw, mwh, n2);
    }

    // 1) input projections (tensor cores): xz = x @ in_proj^T   (2048 x 4096)
    for (int d = 0; d < 2; d++)
        bgemm<<<dim3(2 * DINNER / 128, ML / 128), 256, BG_SMEM_BYTES>>>(
            xh, xl, DMODEL, iph + d * SZ_IP, DMODEL,
            xz + d * SZ_XZ, nullptr, nullptr, 2 * DINNER, DMODEL);

    // 2) depthwise conv + silu
    conv_silu_kernel<<<dim3(ML * DINNER / 256, 2), 256>>>(cw[0], cb[0], cw[1], cb[1]);

    // 3) x_proj (skinny, split-K=8) + reduce
    for (int d = 0; d < 2; d++)
        sgemm_skinny96<<<dim3(ML / 128, 8), 256>>>(
            xc + d * SZ_E, DINNER, xpj[d], DINNER,
            dblp + (size_t)d * 8 * SZ_DBL, DINNER);
    reduce_dbl<<<(2 * ML * DBLW + 255) / 256, 256>>>();

    // 4) delta = softplus(dt @ dt_w^T + dt_b)   (fp32, K=64)
    for (int d = 0; d < 2; d++)
        sgemm_nt<<<dim3(DINNER / 128, ML / 128), 256>>>(
            dbl + d * SZ_DBL, DBLW, dtw[d], DTRANK,
            delta + d * SZ_E, DINNER, DTRANK, dtb[d], 2);

    // 5) selective scan + gating (writes y as fp16 hi/lo)
    scan_kernel<<<dim3(BSZ * DINNER * DSTATE / 128, 2), 128>>>(
        alog[0], Dp[0], alog[1], Dp[1]);

    // 6) output projections (tensor cores): od[:, d*1024:(d+1)*1024] = y @ op^T
    //    written as fp16 hi/lo into the concatenated od buffer (ldc = 2048).
    for (int d = 0; d < 2; d++)
        bgemm<<<dim3(DMODEL / 128, ML / 128), 256, BG_SMEM_BYTES>>>(
            yh + d * SZ_E, yl + d * SZ_E, DINNER,
            oph + d * SZ_OP, DINNER,
            nullptr, odh + d * DMODEL, odl + d * DMODEL, 2 * DMODEL, DINNER);

    // 7) merge (tensor cores): out = odcat @ merge_w^T   (K = 2048, single GEMM)
    bgemm<<<dim3(DMODEL / 128, ML / 128), 256, BG_SMEM_BYTES>>>(
        odh, odl, 2 * DMODEL, mwh, 2 * DMODEL,
        (float*)d_out, nullptr, nullptr, DMODEL, 2 * DMODEL);
}